// round 6
// baseline (speedup 1.0000x reference)
#include <cuda_runtime.h>
#include <cstdint>

// Problem constants
#define B 64
#define S 128
#define L 1024
#define H 512
#define E 256
#define V 64

// ---------------------------------------------------------------------------
// Scratch (single __device__ symbol; no allocation anywhere)
// ---------------------------------------------------------------------------
struct Scratch {
    float h0[2][B * H], c0[2][B * H];   // attention LSTM state (ping-pong)
    float h1[2][B * H], c1[2][B * H];   // rnn layer 0
    float h2[2][B * H], c2[2][B * H];   // rnn layer 1
    float r[B * H];                     // softmax-weighted sum of encoder_h
    float q[B * H];                     // query = P @ h2 + p0
    float hidden[B * H];                // MLP hidden
    float P[H * H];                     // Wh_w^T @ Ws_w
    float p0[H];                        // Wh_w^T @ Ws_b
    float A2[4 * H * H];                // att Wih[:,E:E+H] @ Wh_w  (ctx fold)
    float cbias[4 * H];                 // att Wih[:,E:E+H] @ Wh_b
    float w1b[H * H];                   // W1[:,H:2H] @ Wh_w
    float b1p[H];                       // b1 + W1[:,H:2H] @ Wh_b
    float am[B * 16], az[B * 16];       // per-chunk softmax max / sum
    float ar[B * 16 * H];               // per-chunk weighted partial sums
    int yflag;                          // 1 if y is int64, 0 if int32
};
__device__ Scratch g_s;
__device__ unsigned g_count;            // grid-barrier monotonic counter

// ---------------------------------------------------------------------------
// Grid-wide barrier: monotonic counter, no reset race. g_count zeroed by
// zero_kernel before the persistent kernel each replay. All blocks call the
// same number of times -> target k advances identically everywhere.
// ---------------------------------------------------------------------------
__device__ __forceinline__ void grid_sync(int nblk, unsigned& k) {
    k += (unsigned)nblk;
    __syncthreads();
    if (threadIdx.x == 0) {
        __threadfence();                          // release this block's writes
        atomicAdd(&g_count, 1u);
        while (*((volatile unsigned*)&g_count) < k) __nanosleep(64);
        __threadfence();                          // acquire others' writes
    }
    __syncthreads();
}

// ---------------------------------------------------------------------------
// y dtype detection: values in [0,64) -> if int64 (LE), odd int32 words are 0.
// ---------------------------------------------------------------------------
__global__ void detect_y_kernel(const void* y) {
    if (threadIdx.x == 0 && blockIdx.x == 0) {
        const int* yi = (const int*)y;
        int f = 1;
        for (int i = 0; i < 128; i++) {
            if (yi[2 * i + 1] != 0) { f = 0; break; }
        }
        g_s.yflag = f;
    }
}

__global__ void zero_kernel() {
    int i = blockIdx.x * blockDim.x + threadIdx.x;
    if (i == 0) g_count = 0u;
    if (i < B * H) {
        g_s.h0[0][i] = 0.f; g_s.c0[0][i] = 0.f;
        g_s.h1[0][i] = 0.f; g_s.c1[0][i] = 0.f;
        g_s.h2[0][i] = 0.f; g_s.c2[0][i] = 0.f;
        g_s.r[i] = 0.f;                  // t=0: ctx-region contribution = 0
    }
}

// ---------------------------------------------------------------------------
// One-time precompute kernels (small, run once per replay)
// ---------------------------------------------------------------------------
__global__ void prep_P_kernel(const float* __restrict__ Wh,
                              const float* __restrict__ Ws) {
    __shared__ float As[32][33];
    __shared__ float Bs[32][33];
    int tid = threadIdx.x;
    int tx = tid & 31, ty = tid >> 5;
    int j0 = blockIdx.y * 32, k0 = blockIdx.x * 32;
    float acc[4] = {0.f, 0.f, 0.f, 0.f};
    for (int i0 = 0; i0 < H; i0 += 32) {
        #pragma unroll
        for (int u = 0; u < 4; u++) {
            int idx = tid + u * 256;
            int ii = idx >> 5, cc = idx & 31;
            As[ii][cc] = Wh[(i0 + ii) * H + j0 + cc];
            Bs[ii][cc] = Ws[(i0 + ii) * H + k0 + cc];
        }
        __syncthreads();
        #pragma unroll
        for (int ii = 0; ii < 32; ii++) {
            float bv = Bs[ii][tx];
            #pragma unroll
            for (int rr = 0; rr < 4; rr++) acc[rr] += As[ii][ty + 8 * rr] * bv;
        }
        __syncthreads();
    }
    #pragma unroll
    for (int rr = 0; rr < 4; rr++)
        g_s.P[(j0 + ty + 8 * rr) * H + k0 + tx] = acc[rr];
}

__global__ void prep_p0_kernel(const float* __restrict__ Wh,
                               const float* __restrict__ Wsb) {
    int j = blockIdx.x * blockDim.x + threadIdx.x;
    if (j < H) {
        float a = 0.f;
        for (int i = 0; i < H; i++) a += Wh[i * H + j] * Wsb[i];
        g_s.p0[j] = a;
    }
}

// C[m][n] = sum_k A[m*lda + offA + k] * Bm[k*ldb + n], K = 512
__global__ void prep_gemm_kernel(const float* __restrict__ A, int lda, int offA,
                                 const float* __restrict__ Bm, int ldb,
                                 float* __restrict__ Cm, int ldc) {
    __shared__ float As[32][33];
    __shared__ float Bs[32][33];
    int tid = threadIdx.x;
    int tx = tid & 31, ty = tid >> 5;
    int n0 = blockIdx.x * 32, m0 = blockIdx.y * 32;
    float acc[4] = {0.f, 0.f, 0.f, 0.f};
    for (int k0 = 0; k0 < H; k0 += 32) {
        #pragma unroll
        for (int u = 0; u < 4; u++) {
            int idx = tid + u * 256;
            int rr = idx >> 5, cc = idx & 31;
            As[rr][cc] = A[(m0 + rr) * lda + offA + k0 + cc];
            Bs[rr][cc] = Bm[(k0 + rr) * ldb + n0 + cc];
        }
        __syncthreads();
        #pragma unroll
        for (int kk = 0; kk < 32; kk++) {
            float bv = Bs[kk][tx];
            #pragma unroll
            for (int rr = 0; rr < 4; rr++) acc[rr] += As[ty + 8 * rr][kk] * bv;
        }
        __syncthreads();
    }
    #pragma unroll
    for (int rr = 0; rr < 4; rr++)
        Cm[(m0 + ty + 8 * rr) * ldc + n0 + tx] = acc[rr];
}

__global__ void prep_cbias_kernel(const float* __restrict__ Wih,
                                  const float* __restrict__ Whb) {
    int j = blockIdx.x * blockDim.x + threadIdx.x;
    if (j < 4 * H) {
        float a = 0.f;
        for (int k = 0; k < H; k++) a += Wih[j * (E + H) + E + k] * Whb[k];
        g_s.cbias[j] = a;
    }
}

__global__ void prep_b1p_kernel(const float* __restrict__ W1,
                                const float* __restrict__ b1,
                                const float* __restrict__ Whb) {
    int n = blockIdx.x * blockDim.x + threadIdx.x;
    if (n < H) {
        float a = b1[n];
        for (int k = 0; k < H; k++) a += W1[n * 2 * H + H + k] * Whb[k];
        g_s.b1p[n] = a;
    }
}

// ---------------------------------------------------------------------------
// Register-staging helpers for the LSTM software pipeline
// ---------------------------------------------------------------------------
template <bool ATT, int Kx>
__device__ __forceinline__ void load_x_regs(float (&xr)[32], int k0, int tid,
                                            const int* ysm,
                                            const float* __restrict__ emb,
                                            const float* __restrict__ xlow,
                                            const float* __restrict__ hprev) {
    #pragma unroll
    for (int u = 0; u < 32; u++) {
        int idx = tid + u * 256;
        int bb = idx >> 7, kk = idx & 127;
        int k = k0 + kk;
        float v;
        if (ATT) {
            if (k < E)       v = emb[ysm[bb] * E + k];
            else if (k < Kx) v = g_s.r[bb * H + (k - E)];
            else             v = hprev[bb * H + (k - Kx)];
        } else {
            if (k < Kx) v = xlow[bb * H + k];
            else        v = hprev[bb * H + (k - Kx)];
        }
        xr[u] = v;
    }
}

template <bool ATT, int Kx>
__device__ __forceinline__ void load_w_regs(float (&wr)[8], int k0, int tid,
                                            int jbase,
                                            const float* __restrict__ Wih,
                                            const float* __restrict__ A2p,
                                            const float* __restrict__ Whh) {
    #pragma unroll
    for (int u = 0; u < 8; u++) {
        int idx = tid + u * 256;
        int r16 = idx >> 7, kk = idx & 127;
        int g = r16 >> 2, jj = r16 & 3;
        int row = g * H + jbase + jj;
        int k = k0 + kk;
        float wv;
        if (ATT) {
            if (k < E)       wv = Wih[row * (E + H) + k];
            else if (k < Kx) wv = A2p[row * H + (k - E)];
            else             wv = Whh[row * H + (k - Kx)];
        } else {
            if (k < Kx) wv = Wih[row * H + k];
            else        wv = Whh[row * H + (k - Kx)];
        }
        wr[u] = wv;
    }
}

// ---------------------------------------------------------------------------
// LSTM stage body (one j-quad tile). Block = 64 batch x 4 gate-quads.
// ATT=true : x = [emb(y[:,t]) | r_prev (A2 ctx-fold) | h_prev], K=1280
// ATT=false: x = [x_low | h_prev], K=1024
// ---------------------------------------------------------------------------
template <bool ATT>
__device__ void lstm_body(int jbase, int t,
                          const float* __restrict__ xlow,
                          const void* __restrict__ yptr,
                          const float* __restrict__ emb,
                          const float* __restrict__ hprev,
                          const float* __restrict__ cprev,
                          const float* __restrict__ Wih,
                          const float* __restrict__ A2p,
                          const float* __restrict__ Whh,
                          const float* __restrict__ bih,
                          const float* __restrict__ bhh,
                          float* __restrict__ hout,
                          float* __restrict__ cout,
                          float* sm_base) {
    constexpr int Kx = ATT ? (E + H) : H;
    constexpr int Ktot = Kx + H;            // 1280 or 1024
    constexpr int NCH = Ktot / 128;
    float (*xs)[132] = (float (*)[132])sm_base;                 // 64 x 132
    float (*ws)[128] = (float (*)[128])(sm_base + 64 * 132);    // 16 x 128
    int* ysm = (int*)(sm_base + 64 * 132 + 16 * 128);           // 64 ints

    int tid = threadIdx.x;
    int b = tid & 63, jq = tid >> 6;

    if (ATT) {
        if (tid < B)
            ysm[tid] = g_s.yflag ? (int)((const long long*)yptr)[tid * S + t]
                                 : ((const int*)yptr)[tid * S + t];
        __syncthreads();
    }

    float xr[32], wr[8];
    load_x_regs<ATT, Kx>(xr, 0, tid, ysm, emb, xlow, hprev);
    load_w_regs<ATT, Kx>(wr, 0, tid, jbase, Wih, A2p, Whh);

    float ai = 0.f, af = 0.f, ag = 0.f, ao = 0.f;

    #pragma unroll
    for (int ch = 0; ch < NCH; ch++) {
        #pragma unroll
        for (int u = 0; u < 32; u++) {
            int idx = tid + u * 256;
            xs[idx >> 7][idx & 127] = xr[u];
        }
        #pragma unroll
        for (int u = 0; u < 8; u++) {
            int idx = tid + u * 256;
            ws[idx >> 7][idx & 127] = wr[u];
        }
        __syncthreads();
        if (ch + 1 < NCH) {   // prefetch next chunk; overlaps with compute
            load_x_regs<ATT, Kx>(xr, (ch + 1) * 128, tid, ysm, emb, xlow, hprev);
            load_w_regs<ATT, Kx>(wr, (ch + 1) * 128, tid, jbase, Wih, A2p, Whh);
        }
        #pragma unroll
        for (int kk = 0; kk < 128; kk += 4) {
            float4 xv = *(const float4*)&xs[b][kk];
            float4 wi = *(const float4*)&ws[jq][kk];
            float4 wf = *(const float4*)&ws[4 + jq][kk];
            float4 wg = *(const float4*)&ws[8 + jq][kk];
            float4 wo = *(const float4*)&ws[12 + jq][kk];
            ai += xv.x * wi.x + xv.y * wi.y + xv.z * wi.z + xv.w * wi.w;
            af += xv.x * wf.x + xv.y * wf.y + xv.z * wf.z + xv.w * wf.w;
            ag += xv.x * wg.x + xv.y * wg.y + xv.z * wg.z + xv.w * wg.w;
            ao += xv.x * wo.x + xv.y * wo.y + xv.z * wo.z + xv.w * wo.w;
        }
        __syncthreads();
    }

    int j = jbase + jq;
    float ei = 0.f, ef = 0.f, eg = 0.f, eo = 0.f;
    if (ATT && t > 0) {   // ctx-fold bias: reference's initial att is exactly 0
        ei = g_s.cbias[j];
        ef = g_s.cbias[j + H];
        eg = g_s.cbias[j + 2 * H];
        eo = g_s.cbias[j + 3 * H];
    }
    float gi = ai + bih[j]         + bhh[j]         + ei;
    float gf = af + bih[j + H]     + bhh[j + H]     + ef;
    float gg = ag + bih[j + 2 * H] + bhh[j + 2 * H] + eg;
    float go = ao + bih[j + 3 * H] + bhh[j + 3 * H] + eo;
    float si = 1.f / (1.f + expf(-gi));
    float sf = 1.f / (1.f + expf(-gf));
    float so = 1.f / (1.f + expf(-go));
    float c2 = sf * cprev[b * H + j] + si * tanhf(gg);
    float h2 = so * tanhf(c2);
    cout[b * H + j] = c2;
    hout[b * H + j] = h2;
}

// ---------------------------------------------------------------------------
// Linear stage body (one n-quad tile), split weights for ctx-fold:
// out[b,n] = act(bias[n] + sum_{k<K1} x1[b,k] Wa[n,k] + sum x2[b,k] Wb[n,k])
// ---------------------------------------------------------------------------
template <bool RELU>
__device__ void linear_body(int nbase,
                            const float* __restrict__ x1, int K1,
                            const float* __restrict__ x2,
                            const float* __restrict__ Wa, int ldwa,
                            const float* __restrict__ Wb, int ldwb,
                            int Ktot,
                            const float* __restrict__ bias,
                            float* __restrict__ outp, int ldo, int off,
                            float* sm_base) {
    float (*xs)[132] = (float (*)[132])sm_base;
    float (*ws)[128] = (float (*)[128])(sm_base + 64 * 132);
    int tid = threadIdx.x;
    int b = tid & 63, nq = tid >> 6;
    int K2 = Ktot - K1;
    int NCH = Ktot >> 7;

    float xr[32], wr[2];
    #pragma unroll
    for (int u = 0; u < 32; u++) {
        int idx = tid + u * 256;
        int bb = idx >> 7, kk = idx & 127;
        xr[u] = (kk < K1) ? x1[bb * K1 + kk] : x2[bb * K2 + (kk - K1)];
    }
    #pragma unroll
    for (int u = 0; u < 2; u++) {
        int idx = tid + u * 256;
        int rr = idx >> 7, kk = idx & 127;
        wr[u] = (kk < K1) ? Wa[(nbase + rr) * ldwa + kk]
                          : Wb[(nbase + rr) * ldwb + (kk - K1)];
    }

    float acc = 0.f;
    for (int ch = 0; ch < NCH; ch++) {
        #pragma unroll
        for (int u = 0; u < 32; u++) {
            int idx = tid + u * 256;
            xs[idx >> 7][idx & 127] = xr[u];
        }
        #pragma unroll
        for (int u = 0; u < 2; u++) {
            int idx = tid + u * 256;
            ws[idx >> 7][idx & 127] = wr[u];
        }
        __syncthreads();
        if (ch + 1 < NCH) {
            int k0 = (ch + 1) * 128;
            #pragma unroll
            for (int u = 0; u < 32; u++) {
                int idx = tid + u * 256;
                int bb = idx >> 7, kk = idx & 127;
                int k = k0 + kk;
                xr[u] = (k < K1) ? x1[bb * K1 + k] : x2[bb * K2 + (k - K1)];
            }
            #pragma unroll
            for (int u = 0; u < 2; u++) {
                int idx = tid + u * 256;
                int rr = idx >> 7, kk = idx & 127;
                int k = k0 + kk;
                wr[u] = (k < K1) ? Wa[(nbase + rr) * ldwa + k]
                                 : Wb[(nbase + rr) * ldwb + (k - K1)];
            }
        }
        #pragma unroll
        for (int kk = 0; kk < 128; kk += 4) {
            float4 xv = *(const float4*)&xs[b][kk];
            float4 w = *(const float4*)&ws[nq][kk];
            acc += xv.x * w.x + xv.y * w.y + xv.z * w.z + xv.w * w.w;
        }
        __syncthreads();
    }
    int n = nbase + nq;
    acc += bias[n];
    if (RELU) acc = fmaxf(acc, 0.f);
    outp[b * ldo + off + n] = acc;
}

// ---------------------------------------------------------------------------
// Flash-style attention chunk body: (c, bq) stages enc[bq, c*64:(c+1)*64, :]
// into smem once, computes e, chunk-local (m, Z), unnormalized weighted sum.
// ---------------------------------------------------------------------------
__device__ void attn_body(int c, int bq, const float* __restrict__ enc,
                          float* sm_base) {
    float* s_enc = sm_base;                  // 64 * 512
    float* s_q = sm_base + 64 * H;           // 512
    float* s_e = s_q + H;                    // 64
    float* s_p = s_e + 64;                   // 64
    float* s_m = s_p + 64;                   // 1

    int tid = threadIdx.x;
    const float4* src = (const float4*)(enc + ((size_t)bq * L + (size_t)c * 64) * H);
    float4* dst = (float4*)s_enc;
    #pragma unroll 8
    for (int u = 0; u < 32; u++) dst[tid + u * 256] = src[tid + u * 256];
    if (tid < 128) ((float4*)s_q)[tid] = ((const float4*)(g_s.q + bq * H))[tid];
    __syncthreads();

    int w = tid >> 5, lane = tid & 31;
    for (int l = w; l < 64; l += 8) {
        float sum = 0.f;
        #pragma unroll
        for (int it = 0; it < 16; it++) {
            int j = lane + it * 32;
            sum += s_q[j] * s_enc[l * H + j];
        }
        #pragma unroll
        for (int o = 16; o > 0; o >>= 1) sum += __shfl_xor_sync(0xffffffffu, sum, o);
        if (lane == 0) s_e[l] = sum;
    }
    __syncthreads();
    if (tid < 32) {
        float m = fmaxf(s_e[lane], s_e[lane + 32]);
        #pragma unroll
        for (int o = 16; o > 0; o >>= 1) m = fmaxf(m, __shfl_xor_sync(0xffffffffu, m, o));
        if (lane == 0) *s_m = m;
    }
    __syncthreads();
    if (tid < 64) s_p[tid] = expf(s_e[tid] - *s_m);
    __syncthreads();
    if (tid < 32) {
        float z = s_p[lane] + s_p[lane + 32];
        #pragma unroll
        for (int o = 16; o > 0; o >>= 1) z += __shfl_xor_sync(0xffffffffu, z, o);
        if (lane == 0) {
            g_s.am[bq * 16 + c] = *s_m;
            g_s.az[bq * 16 + c] = z;
        }
    }
    float* rdst = g_s.ar + ((size_t)bq * 16 + c) * H;
    #pragma unroll
    for (int rr = 0; rr < 2; rr++) {
        int j = tid + rr * 256;
        float acc = 0.f;
        #pragma unroll 8
        for (int l = 0; l < 64; l++) acc += s_p[l] * s_enc[l * H + j];
        rdst[j] = acc;
    }
    __syncthreads();   // smem reused by next task / stage
}

// Merge 16 chunk partials for one batch element -> r[bq, :]
__device__ void reduce_body(int bq, float* sm_base) {
    float* sw = sm_base;   // 16 floats
    int tid = threadIdx.x;
    if (tid == 0) {
        float m = -1e30f;
        for (int cc = 0; cc < 16; cc++) m = fmaxf(m, g_s.am[bq * 16 + cc]);
        float Z = 0.f;
        for (int cc = 0; cc < 16; cc++)
            Z += expf(g_s.am[bq * 16 + cc] - m) * g_s.az[bq * 16 + cc];
        for (int cc = 0; cc < 16; cc++)
            sw[cc] = expf(g_s.am[bq * 16 + cc] - m) / Z;
    }
    __syncthreads();
    for (int j = tid; j < H; j += 256) {
        float acc = 0.f;
        #pragma unroll
        for (int cc = 0; cc < 16; cc++)
            acc += sw[cc] * g_s.ar[((size_t)bq * 16 + cc) * H + j];
        g_s.r[bq * H + j] = acc;
    }
    __syncthreads();
}

// ---------------------------------------------------------------------------
// Persistent decoder: the entire 128-step loop in ONE kernel.
// Grid = nblk (<= 128 <= #SMs) blocks x 256 threads, 1 block/SM co-resident.
// ---------------------------------------------------------------------------
__global__ void __launch_bounds__(256, 1)
decoder_kernel(int nblk,
               const void* __restrict__ yptr,
               const float* __restrict__ enc,
               const float* __restrict__ emb,
               const float* __restrict__ aWih, const float* __restrict__ aWhh,
               const float* __restrict__ abih, const float* __restrict__ abhh,
               const float* __restrict__ rWih, const float* __restrict__ rWhh,
               const float* __restrict__ rbih, const float* __restrict__ rbhh,
               const float* __restrict__ W1, const float* __restrict__ W2,
               const float* __restrict__ b2,
               float* __restrict__ out) {
    extern __shared__ __align__(16) float sm[];
    const int bid = blockIdx.x;
    unsigned bk = 0;

    for (int t = 0; t < S; t++) {
        int rp = t & 1, wp = rp ^ 1;

        // S1: attention LSTM (ctx folded via A2 @ r_prev + cbias)
        for (int task = bid; task < 128; task += nblk)
            lstm_body<true>(task * 4, t, nullptr, yptr, emb,
                            g_s.h0[rp], g_s.c0[rp],
                            aWih, g_s.A2, aWhh, abih, abhh,
                            g_s.h0[wp], g_s.c0[wp], sm);
        grid_sync(nblk, bk);

        // S2: rnn layer 0
        for (int task = bid; task < 128; task += nblk)
            lstm_body<false>(task * 4, t, g_s.h0[wp], nullptr, nullptr,
                             g_s.h1[rp], g_s.c1[rp],
                             rWih, nullptr, rWhh, rbih, rbhh,
                             g_s.h1[wp], g_s.c1[wp], sm);
        grid_sync(nblk, bk);

        // S3: rnn layer 1
        for (int task = bid; task < 128; task += nblk)
            lstm_body<false>(task * 4, t, g_s.h1[wp], nullptr, nullptr,
                             g_s.h2[rp], g_s.c2[rp],
                             rWih + 4 * H * H, nullptr, rWhh + 4 * H * H,
                             rbih + 4 * H, rbhh + 4 * H,
                             g_s.h2[wp], g_s.c2[wp], sm);
        grid_sync(nblk, bk);

        // S4: q = P @ h2 + p0
        for (int task = bid; task < 128; task += nblk)
            linear_body<false>(task * 4, g_s.h2[wp], H, nullptr,
                               g_s.P, H, nullptr, 0, H,
                               g_s.p0, g_s.q, H, 0, sm);
        grid_sync(nblk, bk);

        // S5: flash attention chunks (1024 tasks)
        for (int task = bid; task < 1024; task += nblk)
            attn_body(task & 15, task >> 4, enc, sm);
        grid_sync(nblk, bk);

        // S6: softmax merge -> r
        for (int task = bid; task < B; task += nblk)
            reduce_body(task, sm);
        grid_sync(nblk, bk);

        // S7: hidden = relu(W1a@h2 + (W1b@Whw)@r + b1')
        for (int task = bid; task < 128; task += nblk)
            linear_body<true>(task * 4, g_s.h2[wp], H, g_s.r,
                              W1, 2 * H, g_s.w1b, H, 2 * H,
                              g_s.b1p, g_s.hidden, H, 0, sm);
        grid_sync(nblk, bk);

        // S8: logits -> out[(b*S + t)*V + n]  (no barrier; next S1 is hazard-free)
        for (int task = bid; task < V / 4; task += nblk)
            linear_body<false>(task * 4, g_s.hidden, H, nullptr,
                               W2, H, nullptr, 0, H,
                               b2, out, S * V, t * V, sm);
    }
}

// ---------------------------------------------------------------------------
// Host launcher
// ---------------------------------------------------------------------------
extern "C" void kernel_launch(void* const* d_in, const int* in_sizes, int n_in,
                              void* d_out, int out_size) {
    const void*  y    = d_in[0];
    const float* enc  = (const float*)d_in[1];
    const float* emb  = (const float*)d_in[2];
    const float* aWih = (const float*)d_in[3];
    const float* aWhh = (const float*)d_in[4];
    const float* abih = (const float*)d_in[5];
    const float* abhh = (const float*)d_in[6];
    const float* rWih = (const float*)d_in[7];
    const float* rWhh = (const float*)d_in[8];
    const float* rbih = (const float*)d_in[9];
    const float* rbhh = (const float*)d_in[10];
    const float* Wsw  = (const float*)d_in[11];
    const float* Wsb  = (const float*)d_in[12];
    const float* Whw  = (const float*)d_in[13];
    const float* Whb  = (const float*)d_in[14];
    const float* W1   = (const float*)d_in[15];
    const float* b1   = (const float*)d_in[16];
    const float* W2   = (const float*)d_in[17];
    const float* b2   = (const float*)d_in[18];
    float* out = (float*)d_out;

    Scratch* s = nullptr;
    cudaGetSymbolAddress((void**)&s, g_s);

    // smem: max(attention 64*512+512+64+64+1, lstm 64*132+16*128+64) floats
    const int SMEM_BYTES = (64 * H + H + 64 + 64 + 16) * (int)sizeof(float);
    static int configured = -1;
    if (configured < 0) {
        cudaFuncSetAttribute(decoder_kernel,
                             cudaFuncAttributeMaxDynamicSharedMemorySize,
                             SMEM_BYTES);
        configured = 1;
    }

    int dev = 0;
    cudaGetDevice(&dev);
    int sms = 128;
    cudaDeviceGetAttribute(&sms, cudaDevAttrMultiProcessorCount, dev);
    int nblk = sms < 128 ? sms : 128;   // co-residency guaranteed: 1 block/SM

    // Prep (8 tiny nodes) + 1 persistent node => 9-node graph
    detect_y_kernel<<<1, 32>>>(y);
    zero_kernel<<<(B * H + 255) / 256, 256>>>();
    prep_P_kernel<<<dim3(16, 16), 256>>>(Whw, Wsw);
    prep_p0_kernel<<<2, 256>>>(Whw, Wsb);
    prep_gemm_kernel<<<dim3(16, 64), 256>>>(aWih, E + H, E, Whw, H, s->A2, H);
    prep_gemm_kernel<<<dim3(16, 16), 256>>>(W1, 2 * H, H, Whw, H, s->w1b, H);
    prep_cbias_kernel<<<8, 256>>>(aWih, Whb);
    prep_b1p_kernel<<<2, 256>>>(W1, b1, Whb);

    decoder_kernel<<<nblk, 256, SMEM_BYTES>>>(
        nblk, y, enc, emb,
        aWih, aWhh, abih, abhh,
        rWih, rWhh, rbih, rbhh,
        W1, W2, b2, out);
}